// round 3
// baseline (speedup 1.0000x reference)
#include <cuda_runtime.h>
#include <mma.h>
#include <cstdint>

using namespace nvcuda;

#define NROWS 8192
#define FEAT  128

// ---------------- scratch (no allocations allowed) ----------------
__device__ float g_dinv[NROWS];
__device__ float g_y[NROWS * FEAT];    // y[j] = dinv[j] * x[j]
__device__ float g_h[NROWS * FEAT];    // adj @ y

// =================================================================
// Kernel 1: rowsum(adj)+1 -> dinv, and y = dinv * x  (fused)
// one block per row, 256 threads, float4 loads
// =================================================================
__global__ __launch_bounds__(256) void k_rowsum_y(
    const float* __restrict__ adj, const float* __restrict__ x)
{
    const int row = blockIdx.x;
    const int t = threadIdx.x;
    const float4* a4 = reinterpret_cast<const float4*>(adj + (size_t)row * NROWS);

    float s = 0.f;
#pragma unroll
    for (int i = 0; i < 8; i++) {
        float4 v = a4[i * 256 + t];
        s += (v.x + v.y) + (v.z + v.w);
    }
#pragma unroll
    for (int o = 16; o; o >>= 1) s += __shfl_xor_sync(0xffffffffu, s, o);

    __shared__ float ws[8];
    __shared__ float sdinv;
    if ((t & 31) == 0) ws[t >> 5] = s;
    __syncthreads();
    if (t < 32) {
        float v = (t < 8) ? ws[t] : 0.f;
#pragma unroll
        for (int o = 4; o; o >>= 1) v += __shfl_xor_sync(0xffffffffu, v, o);
        if (t == 0) {
            float d = rsqrtf(v + 1.0f);   // +1 for the self loop
            sdinv = d;
            g_dinv[row] = d;
        }
    }
    __syncthreads();
    const float d = sdinv;
    if (t < 32) {
        float4 xv = reinterpret_cast<const float4*>(x + (size_t)row * FEAT)[t];
        float4 yv;
        yv.x = d * xv.x; yv.y = d * xv.y; yv.z = d * xv.z; yv.w = d * xv.w;
        reinterpret_cast<float4*>(g_y + (size_t)row * FEAT)[t] = yv;
    }
}

// =================================================================
// Kernel 2: g_h = adj @ y   (M=8192, N=128, K=8192) tf32 wmma
// BM=64, BN=128(full), BK=32, 256 threads = 8 warps (2x4),
// each warp 32x32 = 2x2 wmma(16x16x8) tiles. 3-stage cp.async.
// =================================================================
constexpr int BM = 64;
constexpr int BK = 32;
constexpr int STAGES = 3;
constexpr int APITCH = BK + 4;      // 36 floats (16B multiple)
constexpr int BPITCH = FEAT + 4;    // 132 floats
constexpr int ITERS = NROWS / BK;   // 256
constexpr int SMEM_BYTES = STAGES * (BM * APITCH + BK * BPITCH) * 4; // 78336

__device__ __forceinline__ void cp16(float* dst, const float* src) {
    uint32_t s = (uint32_t)__cvta_generic_to_shared(dst);
    asm volatile("cp.async.cg.shared.global [%0], [%1], 16;" :: "r"(s), "l"(src));
}
__device__ __forceinline__ void cp_commit() { asm volatile("cp.async.commit_group;"); }
template <int n> __device__ __forceinline__ void cp_wait() {
    asm volatile("cp.async.wait_group %0;" :: "n"(n));
}

__global__ __launch_bounds__(256) void k_gemm(const float* __restrict__ adj)
{
    extern __shared__ float smem[];
    float* As = smem;                               // [STAGES][BM][APITCH]
    float* Bs = smem + STAGES * BM * APITCH;        // [STAGES][BK][BPITCH]

    const int t = threadIdx.x;
    const int rowBase = blockIdx.x * BM;

    auto load_stage = [&](int s, int kit) {
        const int k0 = kit * BK;
        // A tile: 64 x 32 floats = 512 float4
#pragma unroll
        for (int i = 0; i < 2; i++) {
            int lin = t + i * 256;
            int r = lin >> 3, c = (lin & 7) * 4;
            cp16(&As[s * BM * APITCH + r * APITCH + c],
                 adj + (size_t)(rowBase + r) * NROWS + k0 + c);
        }
        // B tile (y): 32 x 128 floats = 1024 float4
#pragma unroll
        for (int i = 0; i < 4; i++) {
            int lin = t + i * 256;
            int r = lin >> 5, c = (lin & 31) * 4;
            cp16(&Bs[s * BK * BPITCH + r * BPITCH + c],
                 g_y + (size_t)(k0 + r) * FEAT + c);
        }
    };

    for (int p = 0; p < STAGES - 1; p++) { load_stage(p, p); cp_commit(); }

    const int wid = t >> 5;
    const int wm = wid >> 2;   // 0..1
    const int wn = wid & 3;    // 0..3

    wmma::fragment<wmma::accumulator, 16, 16, 8, float> acc[2][2];
#pragma unroll
    for (int i = 0; i < 2; i++)
#pragma unroll
        for (int j = 0; j < 2; j++) wmma::fill_fragment(acc[i][j], 0.0f);

    for (int it = 0; it < ITERS; it++) {
        cp_wait<STAGES - 2>();
        __syncthreads();                    // all warps done with stage it-1
        int pf = it + STAGES - 1;
        if (pf < ITERS) load_stage(pf % STAGES, pf);
        cp_commit();

        const float* A = &As[(it % STAGES) * BM * APITCH];
        const float* B = &Bs[(it % STAGES) * BK * BPITCH];
#pragma unroll
        for (int kk = 0; kk < BK / 8; kk++) {
            wmma::fragment<wmma::matrix_a, 16, 16, 8, wmma::precision::tf32, wmma::row_major> af[2];
            wmma::fragment<wmma::matrix_b, 16, 16, 8, wmma::precision::tf32, wmma::row_major> bf[2];
#pragma unroll
            for (int i = 0; i < 2; i++) {
                wmma::load_matrix_sync(af[i], A + (wm * 32 + i * 16) * APITCH + kk * 8, APITCH);
#pragma unroll
                for (int e = 0; e < af[i].num_elements; e++)
                    af[i].x[e] = wmma::__float_to_tf32(af[i].x[e]);
            }
#pragma unroll
            for (int j = 0; j < 2; j++) {
                wmma::load_matrix_sync(bf[j], B + (kk * 8) * BPITCH + wn * 32 + j * 16, BPITCH);
#pragma unroll
                for (int e = 0; e < bf[j].num_elements; e++)
                    bf[j].x[e] = wmma::__float_to_tf32(bf[j].x[e]);
            }
#pragma unroll
            for (int i = 0; i < 2; i++)
#pragma unroll
                for (int j = 0; j < 2; j++)
                    wmma::mma_sync(acc[i][j], af[i], bf[j], acc[i][j]);
        }
    }

#pragma unroll
    for (int i = 0; i < 2; i++)
#pragma unroll
        for (int j = 0; j < 2; j++)
            wmma::store_matrix_sync(
                &g_h[(size_t)(rowBase + wm * 32 + i * 16) * FEAT + wn * 32 + j * 16],
                acc[i][j], FEAT, wmma::mem_row_major);
}

// =================================================================
// Kernel 3: h = dinv_i*(g_h + y);  z = h @ W^T + b;  out = z/max(||z||,eps)
// 64 rows per CTA, tf32 wmma for the 128x128 linear (W from L2).
// =================================================================
__global__ __launch_bounds__(256) void k_epilogue(
    const float* __restrict__ W, const float* __restrict__ bias,
    float* __restrict__ out)
{
    __shared__ float hs[64 * 132];
    const int t = threadIdx.x;
    const int row0 = blockIdx.x * 64;

    // load + transform: h = dinv * (adjy + y)
#pragma unroll
    for (int i = 0; i < 8; i++) {
        int lin = t + i * 256;
        int r = lin >> 5, c = (lin & 31) * 4;
        float4 hv = *reinterpret_cast<const float4*>(g_h + (size_t)(row0 + r) * FEAT + c);
        float4 yv = *reinterpret_cast<const float4*>(g_y + (size_t)(row0 + r) * FEAT + c);
        float d = g_dinv[row0 + r];
        float4 o;
        o.x = d * (hv.x + yv.x); o.y = d * (hv.y + yv.y);
        o.z = d * (hv.z + yv.z); o.w = d * (hv.w + yv.w);
        *reinterpret_cast<float4*>(&hs[r * 132 + c]) = o;
    }
    __syncthreads();

    const int wid = t >> 5, lane = t & 31;
    const int wm = wid >> 2, wn = wid & 3;

    wmma::fragment<wmma::accumulator, 16, 16, 8, float> acc[2][2];
#pragma unroll
    for (int i = 0; i < 2; i++)
#pragma unroll
        for (int j = 0; j < 2; j++) wmma::fill_fragment(acc[i][j], 0.0f);

    // z = h @ W^T : B[k][n] = W[n][k] -> col_major view of row-major W, ld=FEAT
#pragma unroll
    for (int k0 = 0; k0 < FEAT; k0 += 8) {
        wmma::fragment<wmma::matrix_a, 16, 16, 8, wmma::precision::tf32, wmma::row_major> af[2];
        wmma::fragment<wmma::matrix_b, 16, 16, 8, wmma::precision::tf32, wmma::col_major> bf[2];
#pragma unroll
        for (int i = 0; i < 2; i++) {
            wmma::load_matrix_sync(af[i], &hs[(wm * 32 + i * 16) * 132 + k0], 132);
#pragma unroll
            for (int e = 0; e < af[i].num_elements; e++)
                af[i].x[e] = wmma::__float_to_tf32(af[i].x[e]);
        }
#pragma unroll
        for (int j = 0; j < 2; j++) {
            wmma::load_matrix_sync(bf[j], W + (size_t)(wn * 32 + j * 16) * FEAT + k0, FEAT);
#pragma unroll
            for (int e = 0; e < bf[j].num_elements; e++)
                bf[j].x[e] = wmma::__float_to_tf32(bf[j].x[e]);
        }
#pragma unroll
        for (int i = 0; i < 2; i++)
#pragma unroll
            for (int j = 0; j < 2; j++)
                wmma::mma_sync(acc[i][j], af[i], bf[j], acc[i][j]);
    }
    __syncthreads();   // everyone done reading hs before overwrite

#pragma unroll
    for (int i = 0; i < 2; i++)
#pragma unroll
        for (int j = 0; j < 2; j++)
            wmma::store_matrix_sync(&hs[(wm * 32 + i * 16) * 132 + wn * 32 + j * 16],
                                    acc[i][j], 132, wmma::mem_row_major);
    __syncthreads();

    // bias + L2 row-normalize: warp w handles rows 8w..8w+7, lane covers 4 cols
    float4 bv = *reinterpret_cast<const float4*>(bias + lane * 4);
#pragma unroll
    for (int r8 = 0; r8 < 8; r8++) {
        int r = wid * 8 + r8;
        float4 z = *reinterpret_cast<float4*>(&hs[r * 132 + lane * 4]);
        z.x += bv.x; z.y += bv.y; z.z += bv.z; z.w += bv.w;
        float s = z.x * z.x + z.y * z.y + z.z * z.z + z.w * z.w;
#pragma unroll
        for (int o = 16; o; o >>= 1) s += __shfl_xor_sync(0xffffffffu, s, o);
        float inv = 1.0f / fmaxf(sqrtf(s), 1e-12f);
        float4 o4;
        o4.x = z.x * inv; o4.y = z.y * inv; o4.z = z.z * inv; o4.w = z.w * inv;
        *reinterpret_cast<float4*>(out + (size_t)(row0 + r) * FEAT + lane * 4) = o4;
    }
}

// =================================================================
// launch (graph-capturable, no allocs, default stream)
// inputs per metadata order: x [8192,128], adj [8192,8192], W [128,128], b [128]
// =================================================================
extern "C" void kernel_launch(void* const* d_in, const int* in_sizes, int n_in,
                              void* d_out, int out_size)
{
    const float* x   = (const float*)d_in[0];
    const float* adj = (const float*)d_in[1];
    const float* W   = (const float*)d_in[2];
    const float* b   = (const float*)d_in[3];
    float* out = (float*)d_out;

    // Opt in to >48KB dynamic smem. Only do this outside graph capture (the
    // first, uncaptured correctness call); the attribute persists afterwards.
    cudaStreamCaptureStatus cap = cudaStreamCaptureStatusNone;
    cudaStreamIsCapturing((cudaStream_t)0, &cap);
    if (cap == cudaStreamCaptureStatusNone) {
        cudaFuncSetAttribute(k_gemm, cudaFuncAttributeMaxDynamicSharedMemorySize,
                             SMEM_BYTES);
    }

    k_rowsum_y<<<NROWS, 256>>>(adj, x);
    k_gemm<<<NROWS / BM, 256, SMEM_BYTES>>>(adj);
    k_epilogue<<<NROWS / 64, 256>>>(W, b, out);
}

// round 6
// speedup vs baseline: 1.2674x; 1.2674x over previous
#include <cuda_runtime.h>
#include <mma.h>
#include <cstdint>

using namespace nvcuda;

#define NROWS 8192
#define FEAT  128

// ---------------- scratch (no allocations allowed) ----------------
__device__ float g_dinv[NROWS];
__device__ float g_y [NROWS * FEAT];      // y = dinv*x, full fp32 (for k3 self-loop)
__device__ float g_yr[NROWS * FEAT];      // y pre-rounded to tf32 (RN) — GEMM B operand
__device__ float g_hp[2][NROWS * FEAT];   // split-K partials of adj @ y

// ================= helpers =================
__device__ __forceinline__ void cp16s(float* dst, const float* src) {
    uint32_t s = (uint32_t)__cvta_generic_to_shared(dst);
    asm volatile("cp.async.cg.shared.global [%0], [%1], 16;" :: "r"(s), "l"(src));
}
__device__ __forceinline__ void cp_commit() { asm volatile("cp.async.commit_group;"); }
template <int n> __device__ __forceinline__ void cp_wait() {
    asm volatile("cp.async.wait_group %0;" :: "n"(n));
}
__device__ __forceinline__ float tf32rn(float v) {
    float o; asm("cvt.rna.tf32.f32 %0, %1;" : "=f"(o) : "f"(v)); return o;
}

// =================================================================
// Kernel 1: rowsum(adj)+1 -> dinv ; y = dinv*x (fp32) ; yr = tf32RN(y)
// one block per row, 256 threads, float4 loads
// =================================================================
__global__ __launch_bounds__(256) void k_rowsum_y(
    const float* __restrict__ adj, const float* __restrict__ x)
{
    const int row = blockIdx.x;
    const int t = threadIdx.x;
    const float4* a4 = reinterpret_cast<const float4*>(adj + (size_t)row * NROWS);

    float s = 0.f;
#pragma unroll
    for (int i = 0; i < 8; i++) {
        float4 v = a4[i * 256 + t];
        s += (v.x + v.y) + (v.z + v.w);
    }
#pragma unroll
    for (int o = 16; o; o >>= 1) s += __shfl_xor_sync(0xffffffffu, s, o);

    __shared__ float ws[8];
    __shared__ float sdinv;
    if ((t & 31) == 0) ws[t >> 5] = s;
    __syncthreads();
    if (t < 32) {
        float v = (t < 8) ? ws[t] : 0.f;
#pragma unroll
        for (int o = 4; o; o >>= 1) v += __shfl_xor_sync(0xffffffffu, v, o);
        if (t == 0) {
            float d = rsqrtf(v + 1.0f);   // +1 self loop
            sdinv = d;
            g_dinv[row] = d;
        }
    }
    __syncthreads();
    const float d = sdinv;
    if (t < 32) {
        float4 xv = reinterpret_cast<const float4*>(x + (size_t)row * FEAT)[t];
        float4 yv;
        yv.x = d * xv.x; yv.y = d * xv.y; yv.z = d * xv.z; yv.w = d * xv.w;
        reinterpret_cast<float4*>(g_y + (size_t)row * FEAT)[t] = yv;
        float4 yr;
        yr.x = tf32rn(yv.x); yr.y = tf32rn(yv.y);
        yr.z = tf32rn(yv.z); yr.w = tf32rn(yv.w);
        reinterpret_cast<float4*>(g_yr + (size_t)row * FEAT)[t] = yr;
    }
}

// =================================================================
// Kernel 2: g_hp[split] = adj[:, half] @ yr[half, :]
// tf32 wmma (base-ISA HMMA), BM=64, BN=128, BK=32, 3-stage cp.async,
// split-K=2 -> 256 CTAs (~2/SM resident). NO per-element cvts:
// A consumed by HW tf32 truncation (compensated in k3), B pre-rounded.
// =================================================================
constexpr int BM = 64;
constexpr int BK = 32;
constexpr int STAGES = 3;
constexpr int APITCH = BK + 4;      // 36
constexpr int BPITCH = FEAT + 4;    // 132
constexpr int SPLITK = 2;
constexpr int KPER = NROWS / SPLITK;   // 4096
constexpr int ITERS = KPER / BK;       // 128
constexpr int SMEM_BYTES = STAGES * (BM * APITCH + BK * BPITCH) * 4; // 78336

__global__ __launch_bounds__(256, 2) void k_gemm(const float* __restrict__ adj)
{
    extern __shared__ float smem[];
    float* As = smem;                               // [STAGES][BM][APITCH]
    float* Bs = smem + STAGES * BM * APITCH;        // [STAGES][BK][BPITCH]

    const int t = threadIdx.x;
    const int mtile = blockIdx.x >> 1;
    const int split = blockIdx.x & 1;
    const int rowBase = mtile * BM;
    const int kBase = split * KPER;

    auto load_stage = [&](int s, int kit) {
        const int k0 = kBase + kit * BK;
        // A tile: 64 x 32 floats = 512 float4
#pragma unroll
        for (int i = 0; i < 2; i++) {
            int lin = t + i * 256;
            int r = lin >> 3, c = (lin & 7) * 4;
            cp16s(&As[s * BM * APITCH + r * APITCH + c],
                  adj + (size_t)(rowBase + r) * NROWS + k0 + c);
        }
        // B tile (yr): 32 x 128 floats = 1024 float4
#pragma unroll
        for (int i = 0; i < 4; i++) {
            int lin = t + i * 256;
            int r = lin >> 5, c = (lin & 31) * 4;
            cp16s(&Bs[s * BK * BPITCH + r * BPITCH + c],
                  g_yr + (size_t)(k0 + r) * FEAT + c);
        }
    };

#pragma unroll
    for (int p = 0; p < STAGES - 1; p++) { load_stage(p, p); cp_commit(); }

    const int wid = t >> 5;
    const int wm = wid >> 2;   // 0..1
    const int wn = wid & 3;    // 0..3

    wmma::fragment<wmma::accumulator, 16, 16, 8, float> acc[2][2];
#pragma unroll
    for (int i = 0; i < 2; i++)
#pragma unroll
        for (int j = 0; j < 2; j++) wmma::fill_fragment(acc[i][j], 0.0f);

    for (int it = 0; it < ITERS; it++) {
        cp_wait<STAGES - 2>();
        __syncthreads();                  // stage it ready; all warps done with it-1
        int pf = it + STAGES - 1;
        if (pf < ITERS) load_stage(pf % STAGES, pf);
        cp_commit();

        const float* A = &As[(it % STAGES) * BM * APITCH];
        const float* B = &Bs[(it % STAGES) * BK * BPITCH];
#pragma unroll
        for (int kk = 0; kk < BK / 8; kk++) {
            wmma::fragment<wmma::matrix_a, 16, 16, 8, wmma::precision::tf32, wmma::row_major> af[2];
            wmma::fragment<wmma::matrix_b, 16, 16, 8, wmma::precision::tf32, wmma::row_major> bf[2];
#pragma unroll
            for (int i = 0; i < 2; i++)
                wmma::load_matrix_sync(af[i], A + (wm * 32 + i * 16) * APITCH + kk * 8, APITCH);
#pragma unroll
            for (int j = 0; j < 2; j++)
                wmma::load_matrix_sync(bf[j], B + (kk * 8) * BPITCH + wn * 32 + j * 16, BPITCH);
            // NOTE: no __float_to_tf32 — HW truncates (RZ); compensated in k3.
#pragma unroll
            for (int i = 0; i < 2; i++)
#pragma unroll
                for (int j = 0; j < 2; j++)
                    wmma::mma_sync(acc[i][j], af[i], bf[j], acc[i][j]);
        }
    }

#pragma unroll
    for (int i = 0; i < 2; i++)
#pragma unroll
        for (int j = 0; j < 2; j++)
            wmma::store_matrix_sync(
                &g_hp[split][(size_t)(rowBase + wm * 32 + i * 16) * FEAT + wn * 32 + j * 16],
                acc[i][j], FEAT, wmma::mem_row_major);
}

// =================================================================
// Kernel 3: h = dinv_i*(COMP*(hp0+hp1) + y); z = h@W^T + b; L2-normalize
// =================================================================
__global__ __launch_bounds__(256) void k_epilogue(
    const float* __restrict__ W, const float* __restrict__ bias,
    float* __restrict__ out)
{
    __shared__ float hs[64 * 132];
    const int t = threadIdx.x;
    const int row0 = blockIdx.x * 64;
    const float COMP = 1.00048828125f;   // undo tf32 RZ truncation bias on A

#pragma unroll
    for (int i = 0; i < 8; i++) {
        int lin = t + i * 256;
        int r = lin >> 5, c = (lin & 31) * 4;
        size_t idx = (size_t)(row0 + r) * FEAT + c;
        float4 h0 = *reinterpret_cast<const float4*>(&g_hp[0][idx]);
        float4 h1 = *reinterpret_cast<const float4*>(&g_hp[1][idx]);
        float4 yv = *reinterpret_cast<const float4*>(&g_y[idx]);
        float d = g_dinv[row0 + r];
        float4 o;
        o.x = d * (COMP * (h0.x + h1.x) + yv.x);
        o.y = d * (COMP * (h0.y + h1.y) + yv.y);
        o.z = d * (COMP * (h0.z + h1.z) + yv.z);
        o.w = d * (COMP * (h0.w + h1.w) + yv.w);
        *reinterpret_cast<float4*>(&hs[r * 132 + c]) = o;
    }
    __syncthreads();

    const int wid = t >> 5, lane = t & 31;
    const int wm = wid >> 2, wn = wid & 3;

    wmma::fragment<wmma::accumulator, 16, 16, 8, float> acc[2][2];
#pragma unroll
    for (int i = 0; i < 2; i++)
#pragma unroll
        for (int j = 0; j < 2; j++) wmma::fill_fragment(acc[i][j], 0.0f);

    // z = h @ W^T : col_major view of row-major W, ld=FEAT
#pragma unroll
    for (int k0 = 0; k0 < FEAT; k0 += 8) {
        wmma::fragment<wmma::matrix_a, 16, 16, 8, wmma::precision::tf32, wmma::row_major> af[2];
        wmma::fragment<wmma::matrix_b, 16, 16, 8, wmma::precision::tf32, wmma::col_major> bf[2];
#pragma unroll
        for (int i = 0; i < 2; i++) {
            wmma::load_matrix_sync(af[i], &hs[(wm * 32 + i * 16) * 132 + k0], 132);
#pragma unroll
            for (int e = 0; e < af[i].num_elements; e++)
                af[i].x[e] = wmma::__float_to_tf32(af[i].x[e]);
        }
#pragma unroll
        for (int j = 0; j < 2; j++) {
            wmma::load_matrix_sync(bf[j], W + (size_t)(wn * 32 + j * 16) * FEAT + k0, FEAT);
#pragma unroll
            for (int e = 0; e < bf[j].num_elements; e++)
                bf[j].x[e] = wmma::__float_to_tf32(bf[j].x[e]);
        }
#pragma unroll
        for (int i = 0; i < 2; i++)
#pragma unroll
            for (int j = 0; j < 2; j++)
                wmma::mma_sync(acc[i][j], af[i], bf[j], acc[i][j]);
    }
    __syncthreads();

#pragma unroll
    for (int i = 0; i < 2; i++)
#pragma unroll
        for (int j = 0; j < 2; j++)
            wmma::store_matrix_sync(&hs[(wm * 32 + i * 16) * 132 + wn * 32 + j * 16],
                                    acc[i][j], 132, wmma::mem_row_major);
    __syncthreads();

    float4 bv = *reinterpret_cast<const float4*>(bias + lane * 4);
#pragma unroll
    for (int r8 = 0; r8 < 8; r8++) {
        int r = wid * 8 + r8;
        float4 z = *reinterpret_cast<float4*>(&hs[r * 132 + lane * 4]);
        z.x += bv.x; z.y += bv.y; z.z += bv.z; z.w += bv.w;
        float s = z.x * z.x + z.y * z.y + z.z * z.z + z.w * z.w;
#pragma unroll
        for (int o = 16; o; o >>= 1) s += __shfl_xor_sync(0xffffffffu, s, o);
        float inv = 1.0f / fmaxf(sqrtf(s), 1e-12f);
        float4 o4;
        o4.x = z.x * inv; o4.y = z.y * inv; o4.z = z.z * inv; o4.w = z.w * inv;
        *reinterpret_cast<float4*>(out + (size_t)(row0 + r) * FEAT + lane * 4) = o4;
    }
}

// =================================================================
// launch (graph-capturable, no allocs, default stream)
// inputs: x [8192,128], adj [8192,8192], W [128,128], b [128]
// =================================================================
extern "C" void kernel_launch(void* const* d_in, const int* in_sizes, int n_in,
                              void* d_out, int out_size)
{
    const float* x   = (const float*)d_in[0];
    const float* adj = (const float*)d_in[1];
    const float* W   = (const float*)d_in[2];
    const float* b   = (const float*)d_in[3];
    float* out = (float*)d_out;

    cudaStreamCaptureStatus cap = cudaStreamCaptureStatusNone;
    cudaStreamIsCapturing((cudaStream_t)0, &cap);
    if (cap == cudaStreamCaptureStatusNone) {
        cudaFuncSetAttribute(k_gemm, cudaFuncAttributeMaxDynamicSharedMemorySize,
                             SMEM_BYTES);
    }

    k_rowsum_y<<<NROWS, 256>>>(adj, x);
    k_gemm<<<(NROWS / BM) * SPLITK, 256, SMEM_BYTES>>>(adj);
    k_epilogue<<<NROWS / 64, 256>>>(W, b, out);
}

// round 9
// speedup vs baseline: 3.1007x; 2.4465x over previous
#include <cuda_runtime.h>
#include <cuda_fp16.h>
#include <mma.h>
#include <cstdint>

using namespace nvcuda;

#define NROWS 8192
#define FEAT  128

// ---------------- scratch (no allocations allowed) ----------------
__device__ float  g_dinv[NROWS];
__device__ float  g_y [NROWS * FEAT];          // y = dinv*x, fp32 (k3 self-loop term)
__device__ __half g_yh[NROWS * FEAT];          // y in fp16 (GEMM B operand)
__device__ __half g_adjh[(size_t)NROWS * NROWS];  // adj in fp16 (GEMM A operand), 128 MB
__device__ float  g_hp[2][NROWS * FEAT];       // split-K partials of adj @ y

// ================= helpers =================
__device__ __forceinline__ void cp16s(void* dst, const void* src) {
    uint32_t s = (uint32_t)__cvta_generic_to_shared(dst);
    asm volatile("cp.async.cg.shared.global [%0], [%1], 16;" :: "r"(s), "l"(src));
}
__device__ __forceinline__ void cp_commit() { asm volatile("cp.async.commit_group;"); }
template <int n> __device__ __forceinline__ void cp_wait() {
    asm volatile("cp.async.wait_group %0;" :: "n"(n));
}
__device__ __forceinline__ uint32_t h2u(__half2 h) {
    uint32_t u;
    memcpy(&u, &h, 4);
    return u;
}

// =================================================================
// Kernel 1: rowsum(adj)+1 -> dinv ; adjh = fp16(adj) ; y = dinv*x ;
//           yh = fp16(y).  One block per row, 256 threads.
// =================================================================
__global__ __launch_bounds__(256) void k_rowsum_y(
    const float* __restrict__ adj, const float* __restrict__ x)
{
    const int row = blockIdx.x;
    const int t = threadIdx.x;
    const float4* a4 = reinterpret_cast<const float4*>(adj + (size_t)row * NROWS);
    __half* ah = g_adjh + (size_t)row * NROWS;

    float s = 0.f;
#pragma unroll
    for (int i = 0; i < 8; i++) {
        float4 v = a4[i * 256 + t];
        s += (v.x + v.y) + (v.z + v.w);
        // convert this 4-float chunk to fp16 and store (coalesced 8B/thread)
        uint2 pk = make_uint2(h2u(__floats2half2_rn(v.x, v.y)),
                              h2u(__floats2half2_rn(v.z, v.w)));
        *reinterpret_cast<uint2*>(ah + (size_t)(i * 256 + t) * 4) = pk;
    }
#pragma unroll
    for (int o = 16; o; o >>= 1) s += __shfl_xor_sync(0xffffffffu, s, o);

    __shared__ float ws[8];
    __shared__ float sdinv;
    if ((t & 31) == 0) ws[t >> 5] = s;
    __syncthreads();
    if (t < 32) {
        float v = (t < 8) ? ws[t] : 0.f;
#pragma unroll
        for (int o = 4; o; o >>= 1) v += __shfl_xor_sync(0xffffffffu, v, o);
        if (t == 0) {
            float d = rsqrtf(v + 1.0f);   // +1 self loop
            sdinv = d;
            g_dinv[row] = d;
        }
    }
    __syncthreads();
    const float d = sdinv;
    if (t < 32) {
        float4 xv = reinterpret_cast<const float4*>(x + (size_t)row * FEAT)[t];
        float4 yv;
        yv.x = d * xv.x; yv.y = d * xv.y; yv.z = d * xv.z; yv.w = d * xv.w;
        reinterpret_cast<float4*>(g_y + (size_t)row * FEAT)[t] = yv;
        uint2 pk = make_uint2(h2u(__floats2half2_rn(yv.x, yv.y)),
                              h2u(__floats2half2_rn(yv.z, yv.w)));
        *reinterpret_cast<uint2*>(g_yh + (size_t)row * FEAT + t * 4) = pk;
    }
}

// =================================================================
// Kernel 2: g_hp[split] = adjh[:, half] @ yh[half, :]   fp16 HMMA
// BM=64, BN=128, BK=32, 4-stage cp.async, split-K=2 (256 CTAs),
// 8 warps (2x4), warp tile 32x32 via wmma m16n16k16 (LDSM frag loads)
// =================================================================
constexpr int BM = 64;
constexpr int BK = 32;
constexpr int STAGES = 4;
constexpr int APITCH = 40;            // halfs (80B rows: LDSM conflict-free)
constexpr int BPITCH = FEAT + 8;      // 136 halfs (272B rows: conflict-free)
constexpr int SPLITK = 2;
constexpr int KPER = NROWS / SPLITK;  // 4096
constexpr int ITERS = KPER / BK;      // 128
constexpr int A_STAGE = BM * APITCH;  // halfs
constexpr int B_STAGE = BK * BPITCH;  // halfs
constexpr int SMEM_BYTES = STAGES * (A_STAGE + B_STAGE) * 2; // 55296

__global__ __launch_bounds__(256, 2) void k_gemm()
{
    extern __shared__ __half smem[];
    __half* As = smem;                         // [STAGES][BM][APITCH]
    __half* Bs = smem + STAGES * A_STAGE;      // [STAGES][BK][BPITCH]

    const int t = threadIdx.x;
    const int mtile = blockIdx.x >> 1;
    const int split = blockIdx.x & 1;
    const int rowBase = mtile * BM;
    const int kBase = split * KPER;

    auto load_stage = [&](int s, int kit) {
        const int k0 = kBase + kit * BK;
        // A tile: 64 rows x 32 halfs (64B/row) = 256 x 16B chunks, 1/thread
        {
            int r = t >> 2, c = (t & 3) * 8;
            cp16s(&As[s * A_STAGE + r * APITCH + c],
                  g_adjh + (size_t)(rowBase + r) * NROWS + k0 + c);
        }
        // B tile: 32 rows x 128 halfs (256B/row) = 512 chunks, 2/thread
#pragma unroll
        for (int i = 0; i < 2; i++) {
            int lin = t + i * 256;
            int r = lin >> 4, c = (lin & 15) * 8;
            cp16s(&Bs[s * B_STAGE + r * BPITCH + c],
                  g_yh + (size_t)(k0 + r) * FEAT + c);
        }
    };

#pragma unroll
    for (int p = 0; p < STAGES - 1; p++) { load_stage(p, p); cp_commit(); }

    const int wid = t >> 5;
    const int wm = wid >> 2;   // 0..1  (32-row slab)
    const int wn = wid & 3;    // 0..3  (32-col slab)

    wmma::fragment<wmma::accumulator, 16, 16, 16, float> acc[2][2];
#pragma unroll
    for (int i = 0; i < 2; i++)
#pragma unroll
        for (int j = 0; j < 2; j++) wmma::fill_fragment(acc[i][j], 0.0f);

    for (int it = 0; it < ITERS; it++) {
        cp_wait<STAGES - 2>();
        __syncthreads();                  // stage it ready; all warps done with stage it-1
        int pf = it + STAGES - 1;
        if (pf < ITERS) load_stage(pf % STAGES, pf);
        cp_commit();

        const __half* A = &As[(it % STAGES) * A_STAGE];
        const __half* B = &Bs[(it % STAGES) * B_STAGE];
#pragma unroll
        for (int kk = 0; kk < BK / 16; kk++) {
            wmma::fragment<wmma::matrix_a, 16, 16, 16, __half, wmma::row_major> af[2];
            wmma::fragment<wmma::matrix_b, 16, 16, 16, __half, wmma::row_major> bf[2];
#pragma unroll
            for (int i = 0; i < 2; i++)
                wmma::load_matrix_sync(af[i], A + (wm * 32 + i * 16) * APITCH + kk * 16, APITCH);
#pragma unroll
            for (int j = 0; j < 2; j++)
                wmma::load_matrix_sync(bf[j], B + (kk * 16) * BPITCH + wn * 32 + j * 16, BPITCH);
#pragma unroll
            for (int i = 0; i < 2; i++)
#pragma unroll
                for (int j = 0; j < 2; j++)
                    wmma::mma_sync(acc[i][j], af[i], bf[j], acc[i][j]);
        }
    }

#pragma unroll
    for (int i = 0; i < 2; i++)
#pragma unroll
        for (int j = 0; j < 2; j++)
            wmma::store_matrix_sync(
                &g_hp[split][(size_t)(rowBase + wm * 32 + i * 16) * FEAT + wn * 32 + j * 16],
                acc[i][j], FEAT, wmma::mem_row_major);
}

// =================================================================
// Kernel 3: h = dinv_i*((hp0+hp1) + y); z = h@W^T + b; L2-normalize
// =================================================================
__global__ __launch_bounds__(256) void k_epilogue(
    const float* __restrict__ W, const float* __restrict__ bias,
    float* __restrict__ out)
{
    __shared__ float hs[64 * 132];
    const int t = threadIdx.x;
    const int row0 = blockIdx.x * 64;

#pragma unroll
    for (int i = 0; i < 8; i++) {
        int lin = t + i * 256;
        int r = lin >> 5, c = (lin & 31) * 4;
        size_t idx = (size_t)(row0 + r) * FEAT + c;
        float4 h0 = *reinterpret_cast<const float4*>(&g_hp[0][idx]);
        float4 h1 = *reinterpret_cast<const float4*>(&g_hp[1][idx]);
        float4 yv = *reinterpret_cast<const float4*>(&g_y[idx]);
        float d = g_dinv[row0 + r];
        float4 o;
        o.x = d * ((h0.x + h1.x) + yv.x);
        o.y = d * ((h0.y + h1.y) + yv.y);
        o.z = d * ((h0.z + h1.z) + yv.z);
        o.w = d * ((h0.w + h1.w) + yv.w);
        *reinterpret_cast<float4*>(&hs[r * 132 + c]) = o;
    }
    __syncthreads();

    const int wid = t >> 5, lane = t & 31;
    const int wm = wid >> 2, wn = wid & 3;

    wmma::fragment<wmma::accumulator, 16, 16, 8, float> acc[2][2];
#pragma unroll
    for (int i = 0; i < 2; i++)
#pragma unroll
        for (int j = 0; j < 2; j++) wmma::fill_fragment(acc[i][j], 0.0f);

    // z = h @ W^T : col_major view of row-major W, ld=FEAT  (tf32, tiny GEMM)
#pragma unroll
    for (int k0 = 0; k0 < FEAT; k0 += 8) {
        wmma::fragment<wmma::matrix_a, 16, 16, 8, wmma::precision::tf32, wmma::row_major> af[2];
        wmma::fragment<wmma::matrix_b, 16, 16, 8, wmma::precision::tf32, wmma::col_major> bf[2];
#pragma unroll
        for (int i = 0; i < 2; i++) {
            wmma::load_matrix_sync(af[i], &hs[(wm * 32 + i * 16) * 132 + k0], 132);
#pragma unroll
            for (int e = 0; e < af[i].num_elements; e++)
                af[i].x[e] = wmma::__float_to_tf32(af[i].x[e]);
        }
#pragma unroll
        for (int j = 0; j < 2; j++) {
            wmma::load_matrix_sync(bf[j], W + (size_t)(wn * 32 + j * 16) * FEAT + k0, FEAT);
#pragma unroll
            for (int e = 0; e < bf[j].num_elements; e++)
                bf[j].x[e] = wmma::__float_to_tf32(bf[j].x[e]);
        }
#pragma unroll
        for (int i = 0; i < 2; i++)
#pragma unroll
            for (int j = 0; j < 2; j++)
                wmma::mma_sync(acc[i][j], af[i], bf[j], acc[i][j]);
    }
    __syncthreads();

#pragma unroll
    for (int i = 0; i < 2; i++)
#pragma unroll
        for (int j = 0; j < 2; j++)
            wmma::store_matrix_sync(&hs[(wm * 32 + i * 16) * 132 + wn * 32 + j * 16],
                                    acc[i][j], 132, wmma::mem_row_major);
    __syncthreads();

    float4 bv = *reinterpret_cast<const float4*>(bias + lane * 4);
#pragma unroll
    for (int r8 = 0; r8 < 8; r8++) {
        int r = wid * 8 + r8;
        float4 z = *reinterpret_cast<float4*>(&hs[r * 132 + lane * 4]);
        z.x += bv.x; z.y += bv.y; z.z += bv.z; z.w += bv.w;
        float s = z.x * z.x + z.y * z.y + z.z * z.z + z.w * z.w;
#pragma unroll
        for (int o = 16; o; o >>= 1) s += __shfl_xor_sync(0xffffffffu, s, o);
        float inv = 1.0f / fmaxf(sqrtf(s), 1e-12f);
        float4 o4;
        o4.x = z.x * inv; o4.y = z.y * inv; o4.z = z.z * inv; o4.w = z.w * inv;
        *reinterpret_cast<float4*>(out + (size_t)(row0 + r) * FEAT + lane * 4) = o4;
    }
}

// =================================================================
// launch (graph-capturable, no allocs, default stream)
// inputs: x [8192,128], adj [8192,8192], W [128,128], b [128]
// =================================================================
extern "C" void kernel_launch(void* const* d_in, const int* in_sizes, int n_in,
                              void* d_out, int out_size)
{
    const float* x   = (const float*)d_in[0];
    const float* adj = (const float*)d_in[1];
    const float* W   = (const float*)d_in[2];
    const float* b   = (const float*)d_in[3];
    float* out = (float*)d_out;

    cudaStreamCaptureStatus cap = cudaStreamCaptureStatusNone;
    cudaStreamIsCapturing((cudaStream_t)0, &cap);
    if (cap == cudaStreamCaptureStatusNone) {
        cudaFuncSetAttribute(k_gemm, cudaFuncAttributeMaxDynamicSharedMemorySize,
                             SMEM_BYTES);
    }

    k_rowsum_y<<<NROWS, 256>>>(adj, x);
    k_gemm<<<(NROWS / BM) * SPLITK, 256, SMEM_BYTES>>>();
    k_epilogue<<<NROWS / 64, 256>>>(W, b, out);
}